// round 7
// baseline (speedup 1.0000x reference)
#include <cuda_runtime.h>
#include <cuda_bf16.h>
#include <cstdint>

// Problem constants
#define B_    8
#define N_    8192
#define S_    2048
#define D1_   128
#define D2_   256
#define C0_   384          // D1 + D2
#define O1_   256
#define O2_   128
#define ROWS_ 65536        // B_ * N_
#define BN_EPS_ 1e-5f
#define NPART 4
#define SPART (S_ / NPART)   // 512

// ---------------- device scratch (no cudaMalloc allowed) ----------------
__device__ __align__(16) __nv_bfloat16 g_Xh[(size_t)ROWS_ * C0_];  // concat hi
__device__ __align__(16) __nv_bfloat16 g_Xl[(size_t)ROWS_ * C0_];  // concat lo
__device__ __align__(16) float g_Y1[(size_t)ROWS_ * O1_];   // layer1 pre-BN
__device__ __align__(16) float g_Y2[(size_t)ROWS_ * O2_];   // layer2 pre-BN
__device__ __align__(16) float g_f2[(size_t)B_ * S_ * D2_]; // points2 transposed [b][s][d]
__device__ float4 g_p2[B_ * S_];                            // (x,y,z,|p|^2)
__device__ __align__(16) float g_cd[(size_t)ROWS_ * 12];    // split-NN candidate dists
__device__ __align__(16) int   g_ci[(size_t)ROWS_ * 12];    // split-NN candidate idx
__device__ float  g_stats1[2 * O1_];
__device__ float  g_stats2[2 * O2_];
__device__ float  g_sc1[O1_], g_sh1[O1_];
__device__ __align__(16) __nv_bfloat16 g_w1h[O1_ * C0_], g_w1l[O1_ * C0_];
__device__ __align__(16) __nv_bfloat16 g_w2h[O2_ * O1_], g_w2l[O2_ * O1_];

// ---------------- helpers ----------------
__device__ __forceinline__ void bsplit2(float a, float b, uint32_t& h, uint32_t& l) {
    __nv_bfloat162 hv, lv;
    hv.x = __float2bfloat16_rn(a);
    hv.y = __float2bfloat16_rn(b);
    lv.x = __float2bfloat16_rn(a - __bfloat162float(hv.x));
    lv.y = __float2bfloat16_rn(b - __bfloat162float(hv.y));
    h = *reinterpret_cast<uint32_t*>(&hv);
    l = *reinterpret_cast<uint32_t*>(&lv);
}

__device__ __forceinline__ void mma16816(float c[4], const uint32_t a[4],
                                         uint32_t b0, uint32_t b1) {
    asm volatile(
        "mma.sync.aligned.m16n8k16.row.col.f32.bf16.bf16.f32 "
        "{%0,%1,%2,%3}, {%4,%5,%6,%7}, {%8,%9}, {%0,%1,%2,%3};"
        : "+f"(c[0]), "+f"(c[1]), "+f"(c[2]), "+f"(c[3])
        : "r"(a[0]), "r"(a[1]), "r"(a[2]), "r"(a[3]), "r"(b0), "r"(b1));
}

__device__ __forceinline__ void ldsm4(uint32_t r[4], uint32_t addr) {
    asm volatile("ldmatrix.sync.aligned.m8n8.x4.shared.b16 {%0,%1,%2,%3}, [%4];"
        : "=r"(r[0]), "=r"(r[1]), "=r"(r[2]), "=r"(r[3]) : "r"(addr));
}

// ---------------- fused prep: stats zero + xyz2 pack + weight split + both transposes ----------------
// blocks [0,384): misc/weights; [384, 4480): tr_f2; [4480, 12672): tr_f1
#define PRE_BLKS 384
#define TRF2_BLKS 4096   // (S/32)*(D2/32)*B = 64*8*8
#define TRF1_BLKS 8192   // (N/32)*(D1/32)*B = 256*4*8
__global__ __launch_bounds__(256) void k_prep(const float* __restrict__ xyz2,
                      const float* __restrict__ w1, const float* __restrict__ w2,
                      const float* __restrict__ points2, const float* __restrict__ points1) {
    __shared__ float tile[32][33];
    int bid = blockIdx.x;
    int tid = threadIdx.x;
    if (bid < PRE_BLKS) {
        int t = bid * 256 + tid;
        if (t < 2 * O1_) g_stats1[t] = 0.f;
        if (t < 2 * O2_) g_stats2[t] = 0.f;
        if (t < B_ * S_) {
            int b = t / S_, s = t % S_;
            const float* p = xyz2 + (size_t)b * 3 * S_;
            float x = p[s], y = p[S_ + s], z = p[2 * S_ + s];
            g_p2[t] = make_float4(x, y, z, x * x + y * y + z * z);
        }
        if (t < O1_ * C0_) {
            float v = w1[t];
            __nv_bfloat16 h = __float2bfloat16_rn(v);
            g_w1h[t] = h;
            g_w1l[t] = __float2bfloat16_rn(v - __bfloat162float(h));
        }
        if (t < O2_ * O1_) {
            float v = w2[t];
            __nv_bfloat16 h = __float2bfloat16_rn(v);
            g_w2h[t] = h;
            g_w2l[t] = __float2bfloat16_rn(v - __bfloat162float(h));
        }
    } else if (bid < PRE_BLKS + TRF2_BLKS) {
        int rel = bid - PRE_BLKS;
        int s0 = (rel & 63) * 32;
        int d0 = ((rel >> 6) & 7) * 32;
        int b  = rel >> 9;
        int tx = tid & 31, ty = tid >> 5;
        const float* src = points2 + ((size_t)b * D2_ + d0) * S_ + s0;
        #pragma unroll
        for (int i = ty; i < 32; i += 8)
            tile[i][tx] = src[(size_t)i * S_ + tx];
        __syncthreads();
        float* dst = g_f2 + ((size_t)b * S_ + s0) * D2_ + d0;
        #pragma unroll
        for (int i = ty; i < 32; i += 8)
            dst[(size_t)i * D2_ + tx] = tile[tx][i];
    } else {
        int rel = bid - PRE_BLKS - TRF2_BLKS;
        int n0 = (rel & 255) * 32;
        int d0 = ((rel >> 8) & 3) * 32;
        int b  = rel >> 10;
        int tx = tid & 31, ty = tid >> 5;
        const float* src = points1 + ((size_t)b * D1_ + d0) * N_ + n0;
        #pragma unroll
        for (int i = ty; i < 32; i += 8)
            tile[i][tx] = src[(size_t)i * N_ + tx];
        __syncthreads();
        size_t base = ((size_t)(b * N_ + n0)) * C0_ + d0;
        #pragma unroll
        for (int i = ty; i < 32; i += 8) {
            float v = tile[tx][i];
            __nv_bfloat16 h = __float2bfloat16_rn(v);
            g_Xh[base + (size_t)i * C0_ + tx] = h;
            g_Xl[base + (size_t)i * C0_ + tx] = __float2bfloat16_rn(v - __bfloat162float(h));
        }
    }
}

// ---------------- 3-NN split over S, group-of-8 min filter ----------------
__global__ __launch_bounds__(256) void k_nn3p(const float* __restrict__ xyz1) {
    __shared__ float4 sp[SPART];   // 8 KB
    int b = blockIdx.y, part = blockIdx.z;
    int n = blockIdx.x * 256 + threadIdx.x;
    for (int i = threadIdx.x; i < SPART; i += 256)
        sp[i] = g_p2[b * S_ + part * SPART + i];
    __syncthreads();

    const float* q = xyz1 + (size_t)b * 3 * N_;
    float x = q[n], y = q[N_ + n], z = q[2 * N_ + n];
    float nx = -2.f * x, ny = -2.f * y, nz = -2.f * z;

    float d0 = 1e30f, d1 = 1e30f, d2 = 1e30f;
    int i0 = 0, i1 = 0, i2 = 0;
    for (int s0 = 0; s0 < SPART; s0 += 8) {
        float dv[8];
        #pragma unroll
        for (int j = 0; j < 8; j++) {
            float4 p = sp[s0 + j];
            dv[j] = fmaf(p.x, nx, fmaf(p.y, ny, fmaf(p.z, nz, p.w)));
        }
        float m = fminf(fminf(fminf(dv[0], dv[1]), fminf(dv[2], dv[3])),
                        fminf(fminf(dv[4], dv[5]), fminf(dv[6], dv[7])));
        if (m < d2) {
            #pragma unroll
            for (int j = 0; j < 8; j++) {
                float d = dv[j];
                if (d < d2) {
                    if (d < d1) {
                        d2 = d1; i2 = i1;
                        if (d < d0) { d1 = d0; i1 = i0; d0 = d; i0 = s0 + j; }
                        else        { d1 = d;  i1 = s0 + j; }
                    } else { d2 = d; i2 = s0 + j; }
                }
            }
        }
    }
    size_t row = (size_t)b * N_ + n;
    size_t o = row * 12 + part * 3;
    int base = part * SPART;
    g_cd[o + 0] = d0; g_cd[o + 1] = d1; g_cd[o + 2] = d2;
    g_ci[o + 0] = base + i0; g_ci[o + 1] = base + i1; g_ci[o + 2] = base + i2;
}

// ---------------- fused merge(12->3) + gather + interpolate -> split bf16 ----------------
__global__ __launch_bounds__(256) void k_interp(const float* __restrict__ xyz1) {
    __shared__ int   sidx[4][3];
    __shared__ float swt [4][3];
    int t = threadIdx.x;
    if (t < 4) {
        unsigned row = blockIdx.x * 4 + t;
        int b = row / N_, n = row % N_;
        float d0 = 1e30f, d1 = 1e30f, d2 = 1e30f;
        int i0 = 0, i1 = 0, i2 = 0;
        const float* cd = g_cd + (size_t)row * 12;
        const int*   ci = g_ci + (size_t)row * 12;
        #pragma unroll
        for (int j = 0; j < 12; j++) {
            float d = cd[j]; int ix = ci[j];
            if (d < d2) {
                if (d < d1) {
                    d2 = d1; i2 = i1;
                    if (d < d0) { d1 = d0; i1 = i0; d0 = d; i0 = ix; }
                    else        { d1 = d;  i1 = ix; }
                } else { d2 = d; i2 = ix; }
            }
        }
        const float* q = xyz1 + (size_t)b * 3 * N_;
        float x = q[n], y = q[N_ + n], z = q[2 * N_ + n];
        float r1 = x * x + y * y + z * z;
        float t0 = fmaxf(d0 + r1, 1e-10f);
        float t1 = fmaxf(d1 + r1, 1e-10f);
        float t2 = fmaxf(d2 + r1, 1e-10f);
        float w0 = 1.f / t0, w1 = 1.f / t1, w2 = 1.f / t2;
        float inv = 1.f / (w0 + w1 + w2);
        sidx[t][0] = i0; sidx[t][1] = i1; sidx[t][2] = i2;
        swt [t][0] = w0 * inv; swt[t][1] = w1 * inv; swt[t][2] = w2 * inv;
    }
    __syncthreads();
    int lr = t >> 6, ln = t & 63;
    unsigned row = blockIdx.x * 4 + lr;
    int b = row / N_;
    int  i0 = sidx[lr][0], i1 = sidx[lr][1], i2 = sidx[lr][2];
    float w0 = swt[lr][0], w1 = swt[lr][1], w2 = swt[lr][2];
    const float4* f = (const float4*)(g_f2 + (size_t)b * S_ * D2_);
    float4 v0 = f[(size_t)i0 * 64 + ln];
    float4 v1 = f[(size_t)i1 * 64 + ln];
    float4 v2 = f[(size_t)i2 * 64 + ln];
    float4 v;
    v.x = w0 * v0.x + w1 * v1.x + w2 * v2.x;
    v.y = w0 * v0.y + w1 * v1.y + w2 * v2.y;
    v.z = w0 * v0.z + w1 * v1.z + w2 * v2.z;
    v.w = w0 * v0.w + w1 * v1.w + w2 * v2.w;
    uint2 hq, lq;
    bsplit2(v.x, v.y, hq.x, lq.x);
    bsplit2(v.z, v.w, hq.y, lq.y);
    size_t o = (size_t)row * C0_ + D1_ + ln * 4;
    *(uint2*)&g_Xh[o] = hq;
    *(uint2*)&g_Xl[o] = lq;
}

// ---------------- HMMA bf16-split GEMM with ldmatrix + fused BN stats ----------------
#define TILE_STRIDE 40
#define OFF_AH 0
#define OFF_AL 10240
#define OFF_BH 20480
#define OFF_BL 30720
#define STG_BYTES 40960

template<bool FIRST>
__global__ __launch_bounds__(256, 1) void k_gemm_mma(const float* __restrict__ bias) {
    constexpr int KD = FIRST ? C0_ : O1_;
    constexpr int NO = FIRST ? O1_ : O2_;
    constexpr int NCH = KD / 32;

    const __nv_bfloat16* __restrict__ Wh = FIRST ? g_w1h : g_w2h;
    const __nv_bfloat16* __restrict__ Wl = FIRST ? g_w1l : g_w2l;
    float* __restrict__ Y     = FIRST ? g_Y1 : g_Y2;
    float* __restrict__ stats = FIRST ? g_stats1 : g_stats2;

    extern __shared__ char sm[];
    const uint32_t smbase = (uint32_t)__cvta_generic_to_shared(sm);

    const int tid = threadIdx.x;
    const int lane = tid & 31, wid = tid >> 5;
    const int g = lane >> 2, tig = lane & 3;
    const int wm = wid & 1, wn = wid >> 1;
    const int r0 = blockIdx.x * 128;
    const int n0 = blockIdx.y * 128;

    float acc[4][4][4];
    #pragma unroll
    for (int m = 0; m < 4; m++)
        #pragma unroll
        for (int n = 0; n < 4; n++)
            #pragma unroll
            for (int j = 0; j < 4; j++) acc[m][n][j] = 0.f;

    const uint32_t a_off = (uint32_t)((wm * 64 + (lane & 15)) * TILE_STRIDE * 2 + (lane >> 4) * 16);
    const uint32_t b_row = (uint32_t)(((lane >> 4) << 3) + (lane & 7));
    const uint32_t b_off0 = (uint32_t)((wn * 32 + b_row) * TILE_STRIDE * 2 + ((lane >> 3) & 1) * 16);
    const uint32_t b_off1 = (uint32_t)((wn * 32 + 16 + b_row) * TILE_STRIDE * 2 + ((lane >> 3) & 1) * 16);

    const int arow = tid >> 2, aseg = (tid & 3) * 8;
    const int frow = tid >> 1, fhalf = (tid & 1) * 16;

    uint4 rAh[2], rAl[2], rBh[2], rBl[2];

#define LDG_CHUNK(kc) do {                                                        \
        if (FIRST) {                                                              \
            _Pragma("unroll")                                                     \
            for (int i = 0; i < 2; i++) {                                         \
                int row = arow + i * 64;                                          \
                rAh[i] = *(const uint4*)&g_Xh[(size_t)(r0 + row) * C0_ + (kc) + aseg]; \
                rAl[i] = *(const uint4*)&g_Xl[(size_t)(r0 + row) * C0_ + (kc) + aseg]; \
                rBh[i] = *(const uint4*)&Wh[(size_t)(n0 + row) * KD + (kc) + aseg];    \
                rBl[i] = *(const uint4*)&Wl[(size_t)(n0 + row) * KD + (kc) + aseg];    \
            }                                                                     \
        } else {                                                                  \
            const float* ap = g_Y1 + (size_t)(r0 + frow) * O1_ + (kc) + fhalf;    \
            const float* scp = g_sc1 + (kc) + fhalf;                              \
            const float* shp = g_sh1 + (kc) + fhalf;                              \
            _Pragma("unroll")                                                     \
            for (int i = 0; i < 2; i++) {                                         \
                float4 u = *(const float4*)(ap + i * 8);                          \
                float4 v = *(const float4*)(ap + i * 8 + 4);                      \
                float4 scu = *(const float4*)(scp + i * 8);                       \
                float4 shu = *(const float4*)(shp + i * 8);                       \
                float4 scv = *(const float4*)(scp + i * 8 + 4);                   \
                float4 shv = *(const float4*)(shp + i * 8 + 4);                   \
                u.x = fmaxf(fmaf(u.x, scu.x, shu.x), 0.f);                        \
                u.y = fmaxf(fmaf(u.y, scu.y, shu.y), 0.f);                        \
                u.z = fmaxf(fmaf(u.z, scu.z, shu.z), 0.f);                        \
                u.w = fmaxf(fmaf(u.w, scu.w, shu.w), 0.f);                        \
                v.x = fmaxf(fmaf(v.x, scv.x, shv.x), 0.f);                        \
                v.y = fmaxf(fmaf(v.y, scv.y, shv.y), 0.f);                        \
                v.z = fmaxf(fmaf(v.z, scv.z, shv.z), 0.f);                        \
                v.w = fmaxf(fmaf(v.w, scv.w, shv.w), 0.f);                        \
                bsplit2(u.x, u.y, rAh[i].x, rAl[i].x);                            \
                bsplit2(u.z, u.w, rAh[i].y, rAl[i].y);                            \
                bsplit2(v.x, v.y, rAh[i].z, rAl[i].z);                            \
                bsplit2(v.z, v.w, rAh[i].w, rAl[i].w);                            \
            }                                                                     \
            _Pragma("unroll")                                                     \
            for (int i = 0; i < 2; i++) {                                         \
                int row = arow + i * 64;                                          \
                rBh[i] = *(const uint4*)&Wh[(size_t)(n0 + row) * KD + (kc) + aseg];    \
                rBl[i] = *(const uint4*)&Wl[(size_t)(n0 + row) * KD + (kc) + aseg];    \
            }                                                                     \
        }                                                                         \
    } while (0)

#define STS_CHUNK(buf) do {                                                       \
        char* bp = sm + (buf) * STG_BYTES;                                        \
        if (FIRST) {                                                              \
            _Pragma("unroll")                                                     \
            for (int i = 0; i < 2; i++) {                                         \
                int row = arow + i * 64;                                          \
                int off = (row * TILE_STRIDE + aseg) * 2;                         \
                *(uint4*)(bp + OFF_AH + off) = rAh[i];                            \
                *(uint4*)(bp + OFF_AL + off) = rAl[i];                            \
                *(uint4*)(bp + OFF_BH + off) = rBh[i];                            \
                *(uint4*)(bp + OFF_BL + off) = rBl[i];                            \
            }                                                                     \
        } else {                                                                  \
            int offa = (frow * TILE_STRIDE + fhalf) * 2;                          \
            *(uint4*)(bp + OFF_AH + offa)      = rAh[0];                          \
            *(uint4*)(bp + OFF_AH + offa + 16) = rAh[1];                          \
            *(uint4*)(bp + OFF_AL + offa)      = rAl[0];                          \
            *(uint4*)(bp + OFF_AL + offa + 16) = rAl[1];                          \
            _Pragma("unroll")                                                     \
            for (int i = 0; i < 2; i++) {                                         \
                int row = arow + i * 64;                                          \
                int off = (row * TILE_STRIDE + aseg) * 2;                         \
                *(uint4*)(bp + OFF_BH + off) = rBh[i];                            \
                *(uint4*)(bp + OFF_BL + off) = rBl[i];                            \
            }                                                                     \
        }                                                                         \
    } while (0)

    LDG_CHUNK(0);
    STS_CHUNK(0);
    __syncthreads();

    for (int ch = 0; ch < NCH; ch++) {
        if (ch + 1 < NCH) LDG_CHUNK((ch + 1) * 32);

        {
            const uint32_t bufb = smbase + (uint32_t)((ch & 1) * STG_BYTES);
            #pragma unroll
            for (int ko = 0; ko < 2; ko++) {
                const uint32_t kb = (uint32_t)(ko * 32);
                uint32_t ah[4][4], al[4][4], bh01[4], bl01[4], bh23[4], bl23[4];
                #pragma unroll
                for (int mt = 0; mt < 4; mt++) {
                    uint32_t ao = bufb + a_off + (uint32_t)(mt * 16 * TILE_STRIDE * 2) + kb;
                    ldsm4(ah[mt], ao + OFF_AH);
                    ldsm4(al[mt], ao + OFF_AL);
                }
                ldsm4(bh01, bufb + OFF_BH + b_off0 + kb);
                ldsm4(bl01, bufb + OFF_BL + b_off0 + kb);
                ldsm4(bh23, bufb + OFF_BH + b_off1 + kb);
                ldsm4(bl23, bufb + OFF_BL + b_off1 + kb);

                #pragma unroll
                for (int mt = 0; mt < 4; mt++) {
                    mma16816(acc[mt][0], ah[mt], bh01[0], bh01[1]);
                    mma16816(acc[mt][0], ah[mt], bl01[0], bl01[1]);
                    mma16816(acc[mt][0], al[mt], bh01[0], bh01[1]);
                    mma16816(acc[mt][1], ah[mt], bh01[2], bh01[3]);
                    mma16816(acc[mt][1], ah[mt], bl01[2], bl01[3]);
                    mma16816(acc[mt][1], al[mt], bh01[2], bh01[3]);
                    mma16816(acc[mt][2], ah[mt], bh23[0], bh23[1]);
                    mma16816(acc[mt][2], ah[mt], bl23[0], bl23[1]);
                    mma16816(acc[mt][2], al[mt], bh23[0], bh23[1]);
                    mma16816(acc[mt][3], ah[mt], bh23[2], bh23[3]);
                    mma16816(acc[mt][3], ah[mt], bl23[2], bl23[3]);
                    mma16816(acc[mt][3], al[mt], bh23[2], bh23[3]);
                }
            }
        }

        if (ch + 1 < NCH) STS_CHUNK((ch + 1) & 1);
        __syncthreads();
    }
#undef LDG_CHUNK
#undef STS_CHUNK

    float ssum[4][2], ssq[4][2];
    #pragma unroll
    for (int nt = 0; nt < 4; nt++) { ssum[nt][0] = ssum[nt][1] = 0.f; ssq[nt][0] = ssq[nt][1] = 0.f; }

    #pragma unroll
    for (int mt = 0; mt < 4; mt++) {
        int row = r0 + wm * 64 + mt * 16 + g;
        #pragma unroll
        for (int nt = 0; nt < 4; nt++) {
            int col = n0 + wn * 32 + nt * 8 + 2 * tig;
            float bv0 = __ldg(bias + col), bv1 = __ldg(bias + col + 1);
            float v0 = acc[mt][nt][0] + bv0, v1 = acc[mt][nt][1] + bv1;
            float v2 = acc[mt][nt][2] + bv0, v3 = acc[mt][nt][3] + bv1;
            ssum[nt][0] += v0 + v2;  ssum[nt][1] += v1 + v3;
            ssq[nt][0]  += v0 * v0 + v2 * v2;
            ssq[nt][1]  += v1 * v1 + v3 * v3;
            *(float2*)&Y[(size_t)row * NO + col]       = make_float2(v0, v1);
            *(float2*)&Y[(size_t)(row + 8) * NO + col] = make_float2(v2, v3);
        }
    }

    #pragma unroll
    for (int nt = 0; nt < 4; nt++)
        #pragma unroll
        for (int c = 0; c < 2; c++) {
            float s = ssum[nt][c], q = ssq[nt][c];
            s += __shfl_xor_sync(0xFFFFFFFFu, s, 4);
            s += __shfl_xor_sync(0xFFFFFFFFu, s, 8);
            s += __shfl_xor_sync(0xFFFFFFFFu, s, 16);
            q += __shfl_xor_sync(0xFFFFFFFFu, q, 4);
            q += __shfl_xor_sync(0xFFFFFFFFu, q, 8);
            q += __shfl_xor_sync(0xFFFFFFFFu, q, 16);
            if (g == 0) {
                int col = n0 + wn * 32 + nt * 8 + 2 * tig + c;
                atomicAdd(&stats[col], s);
                atomicAdd(&stats[NO + col], q);
            }
        }
}

// ---------------- finalize BN1 params ----------------
__global__ void k_fin1(const float* __restrict__ g, const float* __restrict__ be) {
    int c = threadIdx.x;
    float mean = g_stats1[c] * (1.0f / ROWS_);
    float var  = g_stats1[O1_ + c] * (1.0f / ROWS_) - mean * mean;
    float rstd = rsqrtf(var + BN_EPS_);
    float s = g[c] * rstd;
    g_sc1[c] = s; g_sh1[c] = be[c] - mean * s;
}

// ---------------- BN2(inline finalize) + ReLU + transpose to output [B][128][N] ----------------
__global__ void k_out(float* __restrict__ out,
                      const float* __restrict__ g2, const float* __restrict__ be2) {
    __shared__ float tile[32][33];
    int b = blockIdx.z;
    int n0 = blockIdx.x * 32, o0 = blockIdx.y * 32;
    int tx = threadIdx.x, ty = threadIdx.y;
    int c = o0 + tx;
    float mean = g_stats2[c] * (1.0f / ROWS_);
    float var  = g_stats2[O2_ + c] * (1.0f / ROWS_) - mean * mean;
    float rstd = rsqrtf(var + BN_EPS_);
    float sc = g2[c] * rstd;
    float sh = be2[c] - mean * sc;
    const float* src = g_Y2 + ((size_t)(b * N_ + n0)) * O2_ + o0;
    #pragma unroll
    for (int i = ty; i < 32; i += 8) {
        float v = src[(size_t)i * O2_ + tx];
        tile[i][tx] = fmaxf(fmaf(v, sc, sh), 0.f);
    }
    __syncthreads();
    float* dst = out + ((size_t)b * O2_ + o0) * N_ + n0;
    #pragma unroll
    for (int i = ty; i < 32; i += 8)
        dst[(size_t)i * N_ + tx] = tile[tx][i];
}

// ---------------- launch ----------------
extern "C" void kernel_launch(void* const* d_in, const int* in_sizes, int n_in,
                              void* d_out, int out_size) {
    (void)in_sizes; (void)n_in; (void)out_size;
    const float* xyz1    = (const float*)d_in[0];
    const float* xyz2    = (const float*)d_in[1];
    const float* points1 = (const float*)d_in[2];
    const float* points2 = (const float*)d_in[3];
    const float* w1  = (const float*)d_in[4];
    const float* b1  = (const float*)d_in[5];
    const float* g1  = (const float*)d_in[6];
    const float* be1 = (const float*)d_in[7];
    const float* w2  = (const float*)d_in[8];
    const float* b2  = (const float*)d_in[9];
    const float* g2  = (const float*)d_in[10];
    const float* be2 = (const float*)d_in[11];
    float* out = (float*)d_out;

    const int SMEM = 2 * STG_BYTES;   // 81920
    cudaFuncSetAttribute(k_gemm_mma<true>,  cudaFuncAttributeMaxDynamicSharedMemorySize, SMEM);
    cudaFuncSetAttribute(k_gemm_mma<false>, cudaFuncAttributeMaxDynamicSharedMemorySize, SMEM);

    k_prep<<<PRE_BLKS + TRF2_BLKS + TRF1_BLKS, 256>>>(xyz2, w1, w2, points2, points1); // 0
    k_nn3p<<<dim3(N_ / 256, B_, NPART), 256>>>(xyz1);                                  // 1
    k_interp<<<ROWS_ / 4, 256>>>(xyz1);                                                // 2
    k_gemm_mma<true><<<dim3(ROWS_ / 128, 2), 256, SMEM>>>(b1);                         // 3 (profiled)
    k_fin1<<<1, 256>>>(g1, be1);                                                       // 4
    k_gemm_mma<false><<<dim3(ROWS_ / 128, 1), 256, SMEM>>>(b2);                        // 5
    k_out<<<dim3(N_ / 32, O2_ / 32, B_), dim3(32, 8)>>>(out, g2, be2);                 // 6
}

// round 8
// speedup vs baseline: 1.5193x; 1.5193x over previous
#include <cuda_runtime.h>
#include <cuda_bf16.h>
#include <cstdint>

// Problem constants
#define B_    8
#define N_    8192
#define S_    2048
#define D1_   128
#define D2_   256
#define C0_   384          // D1 + D2
#define O1_   256
#define O2_   128
#define ROWS_ 65536        // B_ * N_
#define BN_EPS_ 1e-5f
#define NPART 4
#define SPART (S_ / NPART)   // 512

// ---------------- device scratch (no cudaMalloc allowed) ----------------
__device__ __align__(16) __nv_bfloat16 g_Xh[(size_t)ROWS_ * C0_];  // concat hi
__device__ __align__(16) __nv_bfloat16 g_Xl[(size_t)ROWS_ * C0_];  // concat lo
__device__ __align__(16) float g_Y1[(size_t)ROWS_ * O1_];   // layer1 pre-BN
__device__ __align__(16) float g_Y2[(size_t)ROWS_ * O2_];   // layer2 pre-BN
__device__ __align__(16) float g_f2[(size_t)B_ * S_ * D2_]; // points2 transposed [b][s][d]
__device__ float4 g_p2[B_ * S_];                            // (x,y,z,|p|^2)
__device__ __align__(16) float g_cd[(size_t)ROWS_ * 12];    // split-NN candidate dists
__device__ __align__(16) int   g_ci[(size_t)ROWS_ * 12];    // split-NN candidate idx
__device__ float  g_stats1[2 * O1_];
__device__ float  g_stats2[2 * O2_];
__device__ float  g_sc1[O1_], g_sh1[O1_];
__device__ __align__(16) __nv_bfloat16 g_w1h[O1_ * C0_], g_w1l[O1_ * C0_];
__device__ __align__(16) __nv_bfloat16 g_w2h[O2_ * O1_], g_w2l[O2_ * O1_];

// ---------------- helpers ----------------
__device__ __forceinline__ void bsplit2(float a, float b, uint32_t& h, uint32_t& l) {
    __nv_bfloat162 hv, lv;
    hv.x = __float2bfloat16_rn(a);
    hv.y = __float2bfloat16_rn(b);
    lv.x = __float2bfloat16_rn(a - __bfloat162float(hv.x));
    lv.y = __float2bfloat16_rn(b - __bfloat162float(hv.y));
    h = *reinterpret_cast<uint32_t*>(&hv);
    l = *reinterpret_cast<uint32_t*>(&lv);
}

__device__ __forceinline__ void mma16816(float c[4], const uint32_t a[4],
                                         uint32_t b0, uint32_t b1) {
    asm volatile(
        "mma.sync.aligned.m16n8k16.row.col.f32.bf16.bf16.f32 "
        "{%0,%1,%2,%3}, {%4,%5,%6,%7}, {%8,%9}, {%0,%1,%2,%3};"
        : "+f"(c[0]), "+f"(c[1]), "+f"(c[2]), "+f"(c[3])
        : "r"(a[0]), "r"(a[1]), "r"(a[2]), "r"(a[3]), "r"(b0), "r"(b1));
}

__device__ __forceinline__ void ldsm4(uint32_t r[4], uint32_t addr) {
    asm volatile("ldmatrix.sync.aligned.m8n8.x4.shared.b16 {%0,%1,%2,%3}, [%4];"
        : "=r"(r[0]), "=r"(r[1]), "=r"(r[2]), "=r"(r[3]) : "r"(addr));
}

#define CPA16(dst, src) \
    asm volatile("cp.async.cg.shared.global [%0], [%1], 16;" :: "r"(dst), "l"(src))
#define CPA_COMMIT() asm volatile("cp.async.commit_group;" ::: "memory")
#define CPA_WAIT0()  asm volatile("cp.async.wait_group 0;" ::: "memory")
#define CPA_WAIT1()  asm volatile("cp.async.wait_group 1;" ::: "memory")

// ---------------- fused prep ----------------
#define PRE_BLKS 384
#define TRF2_BLKS 4096
#define TRF1_BLKS 8192
__global__ __launch_bounds__(256) void k_prep(const float* __restrict__ xyz2,
                      const float* __restrict__ w1, const float* __restrict__ w2,
                      const float* __restrict__ points2, const float* __restrict__ points1) {
    __shared__ float tile[32][33];
    int bid = blockIdx.x;
    int tid = threadIdx.x;
    if (bid < PRE_BLKS) {
        int t = bid * 256 + tid;
        if (t < 2 * O1_) g_stats1[t] = 0.f;
        if (t < 2 * O2_) g_stats2[t] = 0.f;
        if (t < B_ * S_) {
            int b = t / S_, s = t % S_;
            const float* p = xyz2 + (size_t)b * 3 * S_;
            float x = p[s], y = p[S_ + s], z = p[2 * S_ + s];
            g_p2[t] = make_float4(x, y, z, x * x + y * y + z * z);
        }
        if (t < O1_ * C0_) {
            float v = w1[t];
            __nv_bfloat16 h = __float2bfloat16_rn(v);
            g_w1h[t] = h;
            g_w1l[t] = __float2bfloat16_rn(v - __bfloat162float(h));
        }
        if (t < O2_ * O1_) {
            float v = w2[t];
            __nv_bfloat16 h = __float2bfloat16_rn(v);
            g_w2h[t] = h;
            g_w2l[t] = __float2bfloat16_rn(v - __bfloat162float(h));
        }
    } else if (bid < PRE_BLKS + TRF2_BLKS) {
        int rel = bid - PRE_BLKS;
        int s0 = (rel & 63) * 32;
        int d0 = ((rel >> 6) & 7) * 32;
        int b  = rel >> 9;
        int tx = tid & 31, ty = tid >> 5;
        const float* src = points2 + ((size_t)b * D2_ + d0) * S_ + s0;
        #pragma unroll
        for (int i = ty; i < 32; i += 8)
            tile[i][tx] = src[(size_t)i * S_ + tx];
        __syncthreads();
        float* dst = g_f2 + ((size_t)b * S_ + s0) * D2_ + d0;
        #pragma unroll
        for (int i = ty; i < 32; i += 8)
            dst[(size_t)i * D2_ + tx] = tile[tx][i];
    } else {
        int rel = bid - PRE_BLKS - TRF2_BLKS;
        int n0 = (rel & 255) * 32;
        int d0 = ((rel >> 8) & 3) * 32;
        int b  = rel >> 10;
        int tx = tid & 31, ty = tid >> 5;
        const float* src = points1 + ((size_t)b * D1_ + d0) * N_ + n0;
        #pragma unroll
        for (int i = ty; i < 32; i += 8)
            tile[i][tx] = src[(size_t)i * N_ + tx];
        __syncthreads();
        size_t base = ((size_t)(b * N_ + n0)) * C0_ + d0;
        #pragma unroll
        for (int i = ty; i < 32; i += 8) {
            float v = tile[tx][i];
            __nv_bfloat16 h = __float2bfloat16_rn(v);
            g_Xh[base + (size_t)i * C0_ + tx] = h;
            g_Xl[base + (size_t)i * C0_ + tx] = __float2bfloat16_rn(v - __bfloat162float(h));
        }
    }
}

// ---------------- 3-NN split over S (R6-proven insertion loop) ----------------
__global__ __launch_bounds__(256) void k_nn3p(const float* __restrict__ xyz1) {
    __shared__ float4 sp[SPART];   // 8 KB
    int b = blockIdx.y, part = blockIdx.z;
    int n = blockIdx.x * 256 + threadIdx.x;
    for (int i = threadIdx.x; i < SPART; i += 256)
        sp[i] = g_p2[b * S_ + part * SPART + i];
    __syncthreads();

    const float* q = xyz1 + (size_t)b * 3 * N_;
    float x = q[n], y = q[N_ + n], z = q[2 * N_ + n];
    float nx = -2.f * x, ny = -2.f * y, nz = -2.f * z;

    float d0 = 1e30f, d1 = 1e30f, d2 = 1e30f;
    int i0 = 0, i1 = 0, i2 = 0;
    #pragma unroll 8
    for (int s = 0; s < SPART; s++) {
        float4 p = sp[s];
        float d = fmaf(p.x, nx, fmaf(p.y, ny, fmaf(p.z, nz, p.w)));
        if (d < d2) {
            if (d < d1) {
                d2 = d1; i2 = i1;
                if (d < d0) { d1 = d0; i1 = i0; d0 = d; i0 = s; }
                else        { d1 = d;  i1 = s; }
            } else { d2 = d; i2 = s; }
        }
    }
    size_t row = (size_t)b * N_ + n;
    size_t o = row * 12 + part * 3;
    int base = part * SPART;
    g_cd[o + 0] = d0; g_cd[o + 1] = d1; g_cd[o + 2] = d2;
    g_ci[o + 0] = base + i0; g_ci[o + 1] = base + i1; g_ci[o + 2] = base + i2;
}

// ---------------- fused merge(12->3) + gather + interpolate -> split bf16 ----------------
__global__ __launch_bounds__(256) void k_interp(const float* __restrict__ xyz1) {
    __shared__ int   sidx[4][3];
    __shared__ float swt [4][3];
    int t = threadIdx.x;
    if (t < 4) {
        unsigned row = blockIdx.x * 4 + t;
        int b = row / N_, n = row % N_;
        float d0 = 1e30f, d1 = 1e30f, d2 = 1e30f;
        int i0 = 0, i1 = 0, i2 = 0;
        const float* cd = g_cd + (size_t)row * 12;
        const int*   ci = g_ci + (size_t)row * 12;
        #pragma unroll
        for (int j = 0; j < 12; j++) {
            float d = cd[j]; int ix = ci[j];
            if (d < d2) {
                if (d < d1) {
                    d2 = d1; i2 = i1;
                    if (d < d0) { d1 = d0; i1 = i0; d0 = d; i0 = ix; }
                    else        { d1 = d;  i1 = ix; }
                } else { d2 = d; i2 = ix; }
            }
        }
        const float* q = xyz1 + (size_t)b * 3 * N_;
        float x = q[n], y = q[N_ + n], z = q[2 * N_ + n];
        float r1 = x * x + y * y + z * z;
        float t0 = fmaxf(d0 + r1, 1e-10f);
        float t1 = fmaxf(d1 + r1, 1e-10f);
        float t2 = fmaxf(d2 + r1, 1e-10f);
        float w0 = 1.f / t0, w1 = 1.f / t1, w2 = 1.f / t2;
        float inv = 1.f / (w0 + w1 + w2);
        sidx[t][0] = i0; sidx[t][1] = i1; sidx[t][2] = i2;
        swt [t][0] = w0 * inv; swt[t][1] = w1 * inv; swt[t][2] = w2 * inv;
    }
    __syncthreads();
    int lr = t >> 6, ln = t & 63;
    unsigned row = blockIdx.x * 4 + lr;
    int b = row / N_;
    int  i0 = sidx[lr][0], i1 = sidx[lr][1], i2 = sidx[lr][2];
    float w0 = swt[lr][0], w1 = swt[lr][1], w2 = swt[lr][2];
    const float4* f = (const float4*)(g_f2 + (size_t)b * S_ * D2_);
    float4 v0 = f[(size_t)i0 * 64 + ln];
    float4 v1 = f[(size_t)i1 * 64 + ln];
    float4 v2 = f[(size_t)i2 * 64 + ln];
    float4 v;
    v.x = w0 * v0.x + w1 * v1.x + w2 * v2.x;
    v.y = w0 * v0.y + w1 * v1.y + w2 * v2.y;
    v.z = w0 * v0.z + w1 * v1.z + w2 * v2.z;
    v.w = w0 * v0.w + w1 * v1.w + w2 * v2.w;
    uint2 hq, lq;
    bsplit2(v.x, v.y, hq.x, lq.x);
    bsplit2(v.z, v.w, hq.y, lq.y);
    size_t o = (size_t)row * C0_ + D1_ + ln * 4;
    *(uint2*)&g_Xh[o] = hq;
    *(uint2*)&g_Xl[o] = lq;
}

// ---------------- HMMA bf16-split GEMM ----------------
// FIRST: cp.async pipeline, launch_bounds(256,2) -> 2 CTAs/SM.
// !FIRST: LDG+BN+split+STS double buffer, 1 CTA/SM.
#define TILE_STRIDE 40
#define OFF_AH 0
#define OFF_AL 10240
#define OFF_BH 20480
#define OFF_BL 30720
#define STG_BYTES 40960

template<bool FIRST>
__global__ __launch_bounds__(256, FIRST ? 2 : 1) void k_gemm_mma(const float* __restrict__ bias) {
    constexpr int KD = FIRST ? C0_ : O1_;
    constexpr int NO = FIRST ? O1_ : O2_;
    constexpr int NCH = KD / 32;

    const __nv_bfloat16* __restrict__ Wh = FIRST ? g_w1h : g_w2h;
    const __nv_bfloat16* __restrict__ Wl = FIRST ? g_w1l : g_w2l;
    float* __restrict__ Y     = FIRST ? g_Y1 : g_Y2;
    float* __restrict__ stats = FIRST ? g_stats1 : g_stats2;

    extern __shared__ char sm[];
    const uint32_t smbase = (uint32_t)__cvta_generic_to_shared(sm);

    const int tid = threadIdx.x;
    const int lane = tid & 31, wid = tid >> 5;
    const int g = lane >> 2, tig = lane & 3;
    const int wm = wid & 1, wn = wid >> 1;
    const int r0 = blockIdx.x * 128;
    const int n0 = blockIdx.y * 128;

    float acc[4][4][4];
    #pragma unroll
    for (int m = 0; m < 4; m++)
        #pragma unroll
        for (int n = 0; n < 4; n++)
            #pragma unroll
            for (int j = 0; j < 4; j++) acc[m][n][j] = 0.f;

    const uint32_t a_off = (uint32_t)((wm * 64 + (lane & 15)) * TILE_STRIDE * 2 + (lane >> 4) * 16);
    const uint32_t b_row = (uint32_t)(((lane >> 4) << 3) + (lane & 7));
    const uint32_t b_off0 = (uint32_t)((wn * 32 + b_row) * TILE_STRIDE * 2 + ((lane >> 3) & 1) * 16);
    const uint32_t b_off1 = (uint32_t)((wn * 32 + 16 + b_row) * TILE_STRIDE * 2 + ((lane >> 3) & 1) * 16);

    const int arow = tid >> 2, aseg = (tid & 3) * 8;
    const int frow = tid >> 1, fhalf = (tid & 1) * 16;

    // -------- FIRST path: cp.async chunk issue --------
#define CPA_CHUNK(buf, kc) do {                                                   \
        uint32_t bb = smbase + (uint32_t)((buf) * STG_BYTES);                     \
        _Pragma("unroll")                                                         \
        for (int i = 0; i < 2; i++) {                                             \
            int row = arow + i * 64;                                              \
            uint32_t doff = (uint32_t)((row * TILE_STRIDE + aseg) * 2);           \
            CPA16(bb + OFF_AH + doff, (const char*)&g_Xh[(size_t)(r0 + row) * C0_ + (kc) + aseg]); \
            CPA16(bb + OFF_AL + doff, (const char*)&g_Xl[(size_t)(r0 + row) * C0_ + (kc) + aseg]); \
            CPA16(bb + OFF_BH + doff, (const char*)&Wh[(size_t)(n0 + row) * KD + (kc) + aseg]);    \
            CPA16(bb + OFF_BL + doff, (const char*)&Wl[(size_t)(n0 + row) * KD + (kc) + aseg]);    \
        }                                                                         \
        CPA_COMMIT();                                                             \
    } while (0)

    // -------- !FIRST path: LDG+BN+split staging --------
    uint4 rAh[2], rAl[2], rBh[2], rBl[2];

#define LDG_CHUNK2(kc) do {                                                       \
        const float* ap = g_Y1 + (size_t)(r0 + frow) * O1_ + (kc) + fhalf;        \
        const float* scp = g_sc1 + (kc) + fhalf;                                  \
        const float* shp = g_sh1 + (kc) + fhalf;                                  \
        _Pragma("unroll")                                                         \
        for (int i = 0; i < 2; i++) {                                             \
            float4 u = *(const float4*)(ap + i * 8);                              \
            float4 v = *(const float4*)(ap + i * 8 + 4);                          \
            float4 scu = *(const float4*)(scp + i * 8);                           \
            float4 shu = *(const float4*)(shp + i * 8);                           \
            float4 scv = *(const float4*)(scp + i * 8 + 4);                       \
            float4 shv = *(const float4*)(shp + i * 8 + 4);                       \
            u.x = fmaxf(fmaf(u.x, scu.x, shu.x), 0.f);                            \
            u.y = fmaxf(fmaf(u.y, scu.y, shu.y), 0.f);                            \
            u.z = fmaxf(fmaf(u.z, scu.z, shu.z), 0.f);                            \
            u.w = fmaxf(fmaf(u.w, scu.w, shu.w), 0.f);                            \
            v.x = fmaxf(fmaf(v.x, scv.x, shv.x), 0.f);                            \
            v.y = fmaxf(fmaf(v.y, scv.y, shv.y), 0.f);                            \
            v.z = fmaxf(fmaf(v.z, scv.z, shv.z), 0.f);                            \
            v.w = fmaxf(fmaf(v.w, scv.w, shv.w), 0.f);                            \
            bsplit2(u.x, u.y, rAh[i].x, rAl[i].x);                                \
            bsplit2(u.z, u.w, rAh[i].y, rAl[i].y);                                \
            bsplit2(v.x, v.y, rAh[i].z, rAl[i].z);                                \
            bsplit2(v.z, v.w, rAh[i].w, rAl[i].w);                                \
        }                                                                         \
        _Pragma("unroll")                                                         \
        for (int i = 0; i < 2; i++) {                                             \
            int row = arow + i * 64;                                              \
            rBh[i] = *(const uint4*)&Wh[(size_t)(n0 + row) * KD + (kc) + aseg];   \
            rBl[i] = *(const uint4*)&Wl[(size_t)(n0 + row) * KD + (kc) + aseg];   \
        }                                                                         \
    } while (0)

#define STS_CHUNK2(buf) do {                                                      \
        char* bp = sm + (buf) * STG_BYTES;                                        \
        int offa = (frow * TILE_STRIDE + fhalf) * 2;                              \
        *(uint4*)(bp + OFF_AH + offa)      = rAh[0];                              \
        *(uint4*)(bp + OFF_AH + offa + 16) = rAh[1];                              \
        *(uint4*)(bp + OFF_AL + offa)      = rAl[0];                              \
        *(uint4*)(bp + OFF_AL + offa + 16) = rAl[1];                              \
        _Pragma("unroll")                                                         \
        for (int i = 0; i < 2; i++) {                                             \
            int row = arow + i * 64;                                              \
            int off = (row * TILE_STRIDE + aseg) * 2;                             \
            *(uint4*)(bp + OFF_BH + off) = rBh[i];                                \
            *(uint4*)(bp + OFF_BL + off) = rBl[i];                                \
        }                                                                         \
    } while (0)

    // compute on buffer `buf` (B-frags first, then per-mt A; low live-reg count)
#define COMPUTE_CHUNK(buf) do {                                                   \
        const uint32_t bufb = smbase + (uint32_t)((buf) * STG_BYTES);             \
        _Pragma("unroll")                                                         \
        for (int ko = 0; ko < 2; ko++) {                                          \
            const uint32_t kb = (uint32_t)(ko * 32);                              \
            uint32_t bh01[4], bl01[4], bh23[4], bl23[4];                          \
            ldsm4(bh01, bufb + OFF_BH + b_off0 + kb);                             \
            ldsm4(bl01, bufb + OFF_BL + b_off0 + kb);                             \
            ldsm4(bh23, bufb + OFF_BH + b_off1 + kb);                             \
            ldsm4(bl23, bufb + OFF_BL + b_off1 + kb);                             \
            _Pragma("unroll")                                                     \
            for (int mt = 0; mt < 4; mt++) {                                      \
                uint32_t ah[4], al[4];                                            \
                uint32_t ao = bufb + a_off + (uint32_t)(mt * 16 * TILE_STRIDE * 2) + kb; \
                ldsm4(ah, ao + OFF_AH);                                           \
                ldsm4(al, ao + OFF_AL);                                           \
                mma16816(acc[mt][0], ah, bh01[0], bh01[1]);                       \
                mma16816(acc[mt][0], ah, bl01[0], bl01[1]);                       \
                mma16816(acc[mt][0], al, bh01[0], bh01[1]);                       \
                mma16816(acc[mt][1], ah, bh01[2], bh01[3]);                       \
                mma16816(acc[mt][1], ah, bl01[2], bl01[3]);                       \
                mma16816(acc[mt][1], al, bh01[2], bh01[3]);                       \
                mma16816(acc[mt][2], ah, bh23[0], bh23[1]);                       \
                mma16816(acc[mt][2], ah, bl23[0], bl23[1]);                       \
                mma16816(acc[mt][2], al, bh23[0], bh23[1]);                       \
                mma16816(acc[mt][3], ah, bh23[2], bh23[3]);                       \
                mma16816(acc[mt][3], ah, bl23[2], bl23[3]);                       \
                mma16816(acc[mt][3], al, bh23[2], bh23[3]);                       \
            }                                                                     \
        }                                                                         \
    } while (0)

    if (FIRST) {
        CPA_CHUNK(0, 0);
        for (int ch = 0; ch < NCH; ch++) {
            if (ch + 1 < NCH) {
                CPA_CHUNK((ch + 1) & 1, (ch + 1) * 32);
                CPA_WAIT1();
            } else {
                CPA_WAIT0();
            }
            __syncthreads();
            COMPUTE_CHUNK(ch & 1);
            __syncthreads();
        }
    } else {
        LDG_CHUNK2(0);
        STS_CHUNK2(0);
        __syncthreads();
        for (int ch = 0; ch < NCH; ch++) {
            if (ch + 1 < NCH) LDG_CHUNK2((ch + 1) * 32);
            COMPUTE_CHUNK(ch & 1);
            if (ch + 1 < NCH) STS_CHUNK2((ch + 1) & 1);
            __syncthreads();
        }
    }
#undef CPA_CHUNK
#undef LDG_CHUNK2
#undef STS_CHUNK2
#undef COMPUTE_CHUNK

    // ---- epilogue: + bias, store Y, fused per-channel BN stats
    float ssum[4][2], ssq[4][2];
    #pragma unroll
    for (int nt = 0; nt < 4; nt++) { ssum[nt][0] = ssum[nt][1] = 0.f; ssq[nt][0] = ssq[nt][1] = 0.f; }

    #pragma unroll
    for (int mt = 0; mt < 4; mt++) {
        int row = r0 + wm * 64 + mt * 16 + g;
        #pragma unroll
        for (int nt = 0; nt < 4; nt++) {
            int col = n0 + wn * 32 + nt * 8 + 2 * tig;
            float bv0 = __ldg(bias + col), bv1 = __ldg(bias + col + 1);
            float v0 = acc[mt][nt][0] + bv0, v1 = acc[mt][nt][1] + bv1;
            float v2 = acc[mt][nt][2] + bv0, v3 = acc[mt][nt][3] + bv1;
            ssum[nt][0] += v0 + v2;  ssum[nt][1] += v1 + v3;
            ssq[nt][0]  += v0 * v0 + v2 * v2;
            ssq[nt][1]  += v1 * v1 + v3 * v3;
            *(float2*)&Y[(size_t)row * NO + col]       = make_float2(v0, v1);
            *(float2*)&Y[(size_t)(row + 8) * NO + col] = make_float2(v2, v3);
        }
    }

    #pragma unroll
    for (int nt = 0; nt < 4; nt++)
        #pragma unroll
        for (int c = 0; c < 2; c++) {
            float s = ssum[nt][c], q = ssq[nt][c];
            s += __shfl_xor_sync(0xFFFFFFFFu, s, 4);
            s += __shfl_xor_sync(0xFFFFFFFFu, s, 8);
            s += __shfl_xor_sync(0xFFFFFFFFu, s, 16);
            q += __shfl_xor_sync(0xFFFFFFFFu, q, 4);
            q += __shfl_xor_sync(0xFFFFFFFFu, q, 8);
            q += __shfl_xor_sync(0xFFFFFFFFu, q, 16);
            if (g == 0) {
                int col = n0 + wn * 32 + nt * 8 + 2 * tig + c;
                atomicAdd(&stats[col], s);
                atomicAdd(&stats[NO + col], q);
            }
        }
}

// ---------------- finalize BN1 params ----------------
__global__ void k_fin1(const float* __restrict__ g, const float* __restrict__ be) {
    int c = threadIdx.x;
    float mean = g_stats1[c] * (1.0f / ROWS_);
    float var  = g_stats1[O1_ + c] * (1.0f / ROWS_) - mean * mean;
    float rstd = rsqrtf(var + BN_EPS_);
    float s = g[c] * rstd;
    g_sc1[c] = s; g_sh1[c] = be[c] - mean * s;
}

// ---------------- BN2(inline finalize) + ReLU + transpose to output ----------------
__global__ void k_out(float* __restrict__ out,
                      const float* __restrict__ g2, const float* __restrict__ be2) {
    __shared__ float tile[32][33];
    int b = blockIdx.z;
    int n0 = blockIdx.x * 32, o0 = blockIdx.y * 32;
    int tx = threadIdx.x, ty = threadIdx.y;
    int c = o0 + tx;
    float mean = g_stats2[c] * (1.0f / ROWS_);
    float var  = g_stats2[O2_ + c] * (1.0f / ROWS_) - mean * mean;
    float rstd = rsqrtf(var + BN_EPS_);
    float sc = g2[c] * rstd;
    float sh = be2[c] - mean * sc;
    const float* src = g_Y2 + ((size_t)(b * N_ + n0)) * O2_ + o0;
    #pragma unroll
    for (int i = ty; i < 32; i += 8) {
        float v = src[(size_t)i * O2_ + tx];
        tile[i][tx] = fmaxf(fmaf(v, sc, sh), 0.f);
    }
    __syncthreads();
    float* dst = out + ((size_t)b * O2_ + o0) * N_ + n0;
    #pragma unroll
    for (int i = ty; i < 32; i += 8)
        dst[(size_t)i * N_ + tx] = tile[tx][i];
}

// ---------------- launch ----------------
extern "C" void kernel_launch(void* const* d_in, const int* in_sizes, int n_in,
                              void* d_out, int out_size) {
    (void)in_sizes; (void)n_in; (void)out_size;
    const float* xyz1    = (const float*)d_in[0];
    const float* xyz2    = (const float*)d_in[1];
    const float* points1 = (const float*)d_in[2];
    const float* points2 = (const float*)d_in[3];
    const float* w1  = (const float*)d_in[4];
    const float* b1  = (const float*)d_in[5];
    const float* g1  = (const float*)d_in[6];
    const float* be1 = (const float*)d_in[7];
    const float* w2  = (const float*)d_in[8];
    const float* b2  = (const float*)d_in[9];
    const float* g2  = (const float*)d_in[10];
    const float* be2 = (const float*)d_in[11];
    float* out = (float*)d_out;

    const int SMEM = 2 * STG_BYTES;   // 81920
    cudaFuncSetAttribute(k_gemm_mma<true>,  cudaFuncAttributeMaxDynamicSharedMemorySize, SMEM);
    cudaFuncSetAttribute(k_gemm_mma<false>, cudaFuncAttributeMaxDynamicSharedMemorySize, SMEM);

    k_prep<<<PRE_BLKS + TRF2_BLKS + TRF1_BLKS, 256>>>(xyz2, w1, w2, points2, points1); // 0
    k_nn3p<<<dim3(N_ / 256, B_, NPART), 256>>>(xyz1);                                  // 1
    k_interp<<<ROWS_ / 4, 256>>>(xyz1);                                                // 2
    k_gemm_mma<true><<<dim3(ROWS_ / 128, 2), 256, SMEM>>>(b1);                         // 3 (profiled)
    k_fin1<<<1, 256>>>(g1, be1);                                                       // 4
    k_gemm_mma<false><<<dim3(ROWS_ / 128, 1), 256, SMEM>>>(b2);                        // 5
    k_out<<<dim3(N_ / 32, O2_ / 32, B_), dim3(32, 8)>>>(out, g2, be2);                 // 6
}